// round 4
// baseline (speedup 1.0000x reference)
#include <cuda_runtime.h>
#include <mma.h>
#include <cstdint>
#include <cstddef>
using namespace nvcuda;

#define TS   512
#define BATCH 128
#define D    512
#define H    512
#define NG3  1536
#define MT   (TS*BATCH)
#define NGC  128
#define BH_  ((size_t)BATCH*H)
#define TBH_ ((size_t)TS*BATCH*H)
#define LDW  516
#define REC_SMEM ((48*LDW + 32*LDW + 32*48)*4)

__device__ float    g_Gx[(size_t)MT*NG3];
__device__ float    g_Fx[(size_t)MT*2];
__device__ float    g_Wx[(size_t)NG3*D];
__device__ float    g_Whh[(size_t)NG3*H];
__device__ float    g_bias[NG3];
__device__ float    g_f[(size_t)TS*BATCH];
__device__ unsigned g_done[TS];
__device__ unsigned g_fdone[TS];

__device__ __forceinline__ float t32(float x){ return wmma::__float_to_tf32(x); }
__device__ __forceinline__ float sigm(float x){ return 1.f/(1.f+expf(-x)); }

// ---------- prep: pack weights (tf32-rounded) + zero counters ----------
__global__ void prep_kernel(const float* __restrict__ Wi, const float* __restrict__ Wu,
                            const float* __restrict__ Wo, const float* __restrict__ bi,
                            const float* __restrict__ bu, const float* __restrict__ bo) {
    int n = blockIdx.x;
    if (n < NG3) {
        int g = n >> 9, j = n & 511;
        const float* W = (g==0) ? Wi : (g==1 ? Wu : Wo);
        const float* s = W + (size_t)j*(D+H);
        for (int k = threadIdx.x; k < D; k += blockDim.x) {
            g_Wx [(size_t)n*D + k] = t32(s[k]);
            g_Whh[(size_t)n*H + k] = t32(s[D+k]);
        }
        if (threadIdx.x == 0) g_bias[n] = (g==0 ? bi : (g==1 ? bu : bo))[j];
    } else {
        for (int k = threadIdx.x; k < TS; k += blockDim.x) { g_done[k]=0u; g_fdone[k]=0u; }
    }
}

// ---------- x-part of forget logits (fp32 exact) ----------
__global__ void fx_kernel(const float* __restrict__ X, const float* __restrict__ Wf,
                          const float* __restrict__ bf) {
    int m = blockIdx.x*8 + (threadIdx.x>>5);
    int lane = threadIdx.x & 31;
    const float* x = X + (size_t)m*D;
    float s0 = 0.f, s1 = 0.f;
    #pragma unroll 4
    for (int k = lane; k < D; k += 32) {
        float xv = x[k];
        s0 += xv * __ldg(&Wf[k]);
        s1 += xv * __ldg(&Wf[1024+k]);
    }
    #pragma unroll
    for (int o = 16; o; o >>= 1) {
        s0 += __shfl_xor_sync(~0u, s0, o);
        s1 += __shfl_xor_sync(~0u, s1, o);
    }
    if (lane == 0) {
        g_Fx[(size_t)m*2+0] = s0 + __ldg(&bf[0]);
        g_Fx[(size_t)m*2+1] = s1 + __ldg(&bf[1]);
    }
}

// ---------- big parallel GEMM: Gx = X @ Wx.T (tf32 WMMA) ----------
__global__ void __launch_bounds__(256) gemm_x(const float* __restrict__ X) {
    __shared__ float As[128*36];
    __shared__ float Bs[64*36];
    int tid = threadIdx.x, wid = tid>>5;
    int m0 = blockIdx.y*128, n0 = blockIdx.x*64;
    int wm = wid>>1, wn = wid&1;
    wmma::fragment<wmma::accumulator,16,16,8,float> acc[2][2];
    #pragma unroll
    for (int i=0;i<2;i++) { wmma::fill_fragment(acc[i][0],0.f); wmma::fill_fragment(acc[i][1],0.f); }

    for (int k0 = 0; k0 < D; k0 += 32) {
        #pragma unroll
        for (int u = 0; u < 4; u++) {
            int f4 = tid + u*256; int r = f4>>3, c4 = f4&7;
            float4 v = *(const float4*)(X + (size_t)(m0+r)*D + k0 + c4*4);
            float* d = &As[r*36 + c4*4];
            d[0]=t32(v.x); d[1]=t32(v.y); d[2]=t32(v.z); d[3]=t32(v.w);
        }
        #pragma unroll
        for (int u = 0; u < 2; u++) {
            int f4 = tid + u*256; int r = f4>>3, c4 = f4&7;
            float4 v = *(const float4*)(g_Wx + (size_t)(n0+r)*D + k0 + c4*4);
            float* d = &Bs[r*36 + c4*4];
            d[0]=v.x; d[1]=v.y; d[2]=v.z; d[3]=v.w;
        }
        __syncthreads();
        #pragma unroll
        for (int kk = 0; kk < 4; kk++) {
            wmma::fragment<wmma::matrix_a,16,16,8,wmma::precision::tf32,wmma::row_major> a0,a1;
            wmma::fragment<wmma::matrix_b,16,16,8,wmma::precision::tf32,wmma::col_major> b0,b1;
            wmma::load_matrix_sync(a0, &As[(wm*32+ 0)*36 + kk*8], 36);
            wmma::load_matrix_sync(a1, &As[(wm*32+16)*36 + kk*8], 36);
            wmma::load_matrix_sync(b0, &Bs[(wn*32+ 0)*36 + kk*8], 36);
            wmma::load_matrix_sync(b1, &Bs[(wn*32+16)*36 + kk*8], 36);
            wmma::mma_sync(acc[0][0], a0, b0, acc[0][0]);
            wmma::mma_sync(acc[0][1], a0, b1, acc[0][1]);
            wmma::mma_sync(acc[1][0], a1, b0, acc[1][0]);
            wmma::mma_sync(acc[1][1], a1, b1, acc[1][1]);
        }
        __syncthreads();
    }
    #pragma unroll
    for (int i=0;i<2;i++)
        #pragma unroll
        for (int j=0;j<2;j++)
            wmma::store_matrix_sync(g_Gx + (size_t)(m0+wm*32+i*16)*NG3 + n0+wn*32+j*16,
                                    acc[i][j], NG3, wmma::mem_row_major);
}

// ---------- persistent recurrent kernel: 128 gate CTAs + 1 f-CTA ----------
__global__ void __launch_bounds__(256,1) rec_kernel(
        float* __restrict__ out, const float* __restrict__ Wf,
        const float* __restrict__ Ws1, const float* __restrict__ bs1,
        const float* __restrict__ Ws2, const float* __restrict__ bs2,
        long long out_size) {
    extern __shared__ float sm[];
    int tid = threadIdx.x, wid = tid>>5, lane = tid&31;
    bool tail = out_size >= (long long)(TBH_ + 2*BH_);

    if (blockIdx.x == NGC) {
        // ---- f-CTA: softmax forget gate (fp32 exact) ----
        float* sWf = sm; // 1024 floats
        for (int k = tid; k < 512; k += 256) { sWf[k] = Wf[512+k]; sWf[512+k] = Wf[1536+k]; }
        float w1[8], b1v[4], w2[8];
        #pragma unroll
        for (int i=0;i<8;i++){ w1[i]=Ws1[i]; w2[i]=Ws2[i]; }
        #pragma unroll
        for (int i=0;i<4;i++) b1v[i]=bs1[i];
        float db = bs2[0]-bs2[1];
        __syncthreads();
        for (int t = 0; t < TS; t++) {
            if (t > 0) {
                if (tid == 0) { volatile unsigned* p = &g_done[t-1]; while (*p < NGC) {} }
                __syncthreads();
            }
            for (int b = wid; b < BATCH; b += 8) {
                float s0 = 0.f, s1 = 0.f;
                if (t > 0) {
                    const float* hr = out + (size_t)(t-1)*BH_ + (size_t)b*H;
                    #pragma unroll 4
                    for (int k = lane; k < H; k += 32) {
                        float hv = hr[k];
                        s0 += hv*sWf[k]; s1 += hv*sWf[512+k];
                    }
                    #pragma unroll
                    for (int o=16;o;o>>=1){ s0+=__shfl_xor_sync(~0u,s0,o); s1+=__shfl_xor_sync(~0u,s1,o); }
                }
                if (lane == 0) {
                    float fl0 = g_Fx[((size_t)t*BATCH+b)*2]   + s0;
                    float fl1 = g_Fx[((size_t)t*BATCH+b)*2+1] + s1;
                    float h0 = tanhf(w1[0]*fl0+w1[1]*fl1+b1v[0]);
                    float h1 = tanhf(w1[2]*fl0+w1[3]*fl1+b1v[1]);
                    float h2 = tanhf(w1[4]*fl0+w1[5]*fl1+b1v[2]);
                    float h3 = tanhf(w1[6]*fl0+w1[7]*fl1+b1v[3]);
                    float dl = (w2[0]-w2[4])*h0+(w2[1]-w2[5])*h1+(w2[2]-w2[6])*h2+(w2[3]-w2[7])*h3+db;
                    g_f[(size_t)t*BATCH+b] = sigm(dl);
                }
            }
            __threadfence();
            __syncthreads();
            if (tid == 0) atomicExch(&g_fdone[t], 1u);
        }
        return;
    }

    // ---- gate CTA: rows [row0,row0+32), gate cols [j0,j0+16) x 3 gates ----
    float* sW = sm;                   // 48*LDW
    float* sA = sm + 48*LDW;          // 32*LDW
    float* sO = sA + 32*LDW;          // 32*48
    int rb = blockIdx.x >> 5, jt = blockIdx.x & 31;
    int row0 = rb*32, j0 = jt*16;
    for (int idx = tid; idx < 48*512; idx += 256) {
        int row = idx >> 9, k = idx & 511;
        sW[row*LDW + k] = g_Whh[(size_t)((row>>4)*512 + j0 + (row&15))*H + k];
    }
    int p0 = tid, p1 = tid + 256;
    int r0p = p0>>4, j0p = p0&15, r1p = p1>>4, j1p = p1&15;
    int b0 = row0+r0p, b1 = row0+r1p;
    int jj0 = j0+j0p, jj1 = j0+j1p;
    float bi0 = g_bias[jj0], bu0 = g_bias[512+jj0], bo0 = g_bias[1024+jj0];
    float bi1 = g_bias[jj1], bu1 = g_bias[512+jj1], bo1 = g_bias[1024+jj1];
    float c0 = 0.f, c1 = 0.f;
    int wr = wid & 1, wc = wid >> 1;
    __syncthreads();

    for (int t = 0; t < TS; t++) {
        if (t > 0) {
            if (tid == 0) { volatile unsigned* p = &g_done[t-1]; while (*p < NGC) {} }
            __syncthreads();
            const float* hb = out + (size_t)(t-1)*BH_;
            #pragma unroll 4
            for (int u = 0; u < 16; u++) {
                int f4 = tid + u*256;
                int r = f4 >> 7, c4 = f4 & 127;
                float4 v = *(const float4*)(hb + (size_t)(row0+r)*H + c4*4);
                float* d = &sA[r*LDW + c4*4];
                d[0]=t32(v.x); d[1]=t32(v.y); d[2]=t32(v.z); d[3]=t32(v.w);
            }
            __syncthreads();
        }
        wmma::fragment<wmma::accumulator,16,16,8,float> acc;
        wmma::fill_fragment(acc, 0.f);
        if (wid < 6) {
            if (t > 0) {
                #pragma unroll 4
                for (int kk = 0; kk < 64; kk++) {
                    wmma::fragment<wmma::matrix_a,16,16,8,wmma::precision::tf32,wmma::row_major> af;
                    wmma::fragment<wmma::matrix_b,16,16,8,wmma::precision::tf32,wmma::col_major> bfr;
                    wmma::load_matrix_sync(af,  &sA[(wr*16)*LDW + kk*8], LDW);
                    wmma::load_matrix_sync(bfr, &sW[(wc*16)*LDW + kk*8], LDW);
                    wmma::mma_sync(acc, af, bfr, acc);
                }
            }
            wmma::store_matrix_sync(&sO[(wr*16)*48 + wc*16], acc, 48, wmma::mem_row_major);
        }
        if (tid == 0) { volatile unsigned* p = &g_fdone[t]; while (*p == 0u) {} }
        __syncthreads();

        size_t gb0 = ((size_t)t*BATCH + b0)*NG3, gb1 = ((size_t)t*BATCH + b1)*NG3;
        float f0 = g_f[(size_t)t*BATCH + b0], f1 = g_f[(size_t)t*BATCH + b1];
        float pi0 = sO[r0p*48 + j0p]      + g_Gx[gb0 + jj0]       + bi0;
        float pu0 = sO[r0p*48 + 16 + j0p] + g_Gx[gb0 + 512+jj0]   + bu0;
        float po0 = sO[r0p*48 + 32 + j0p] + g_Gx[gb0 + 1024+jj0]  + bo0;
        float pi1 = sO[r1p*48 + j1p]      + g_Gx[gb1 + jj1]       + bi1;
        float pu1 = sO[r1p*48 + 16 + j1p] + g_Gx[gb1 + 512+jj1]   + bu1;
        float po1 = sO[r1p*48 + 32 + j1p] + g_Gx[gb1 + 1024+jj1]  + bo1;
        c0 = f0*c0 + sigm(pi0)*tanhf(pu0);
        c1 = f1*c1 + sigm(pi1)*tanhf(pu1);
        float h0 = sigm(po0)*tanhf(c0);
        float h1 = sigm(po1)*tanhf(c1);
        out[(size_t)t*BH_ + (size_t)b0*H + jj0] = h0;
        out[(size_t)t*BH_ + (size_t)b1*H + jj1] = h1;
        if (t == TS-1 && tail) {
            out[TBH_ + (size_t)b0*H + jj0] = h0;
            out[TBH_ + (size_t)b1*H + jj1] = h1;
            out[TBH_ + BH_ + (size_t)b0*H + jj0] = c0;
            out[TBH_ + BH_ + (size_t)b1*H + jj1] = c1;
        }
        __threadfence();
        __syncthreads();
        if (tid == 0) atomicAdd(&g_done[t], 1u);
    }
}

extern "C" void kernel_launch(void* const* d_in, const int* in_sizes, int n_in,
                              void* d_out, int out_size) {
    const float* X   = (const float*)d_in[0];
    const float* Wf  = (const float*)d_in[1];
    const float* bf  = (const float*)d_in[2];
    const float* Wi  = (const float*)d_in[3];
    const float* bi  = (const float*)d_in[4];
    const float* Wu  = (const float*)d_in[5];
    const float* bu  = (const float*)d_in[6];
    const float* Wo  = (const float*)d_in[7];
    const float* bo  = (const float*)d_in[8];
    const float* Ws1 = (const float*)d_in[9];
    const float* bs1 = (const float*)d_in[10];
    const float* Ws2 = (const float*)d_in[11];
    const float* bs2 = (const float*)d_in[12];
    float* out = (float*)d_out;

    cudaFuncSetAttribute(rec_kernel, cudaFuncAttributeMaxDynamicSharedMemorySize, REC_SMEM);

    prep_kernel<<<NG3+1, 128>>>(Wi, Wu, Wo, bi, bu, bo);
    fx_kernel<<<MT/8, 256>>>(X, Wf, bf);
    dim3 g(NG3/64, MT/128);
    gemm_x<<<g, 256>>>(X);
    rec_kernel<<<NGC+1, 256, REC_SMEM>>>(out, Wf, Ws1, bs1, Ws2, bs2, (long long)out_size);
}

// round 5
// speedup vs baseline: 1.8766x; 1.8766x over previous
#include <cuda_runtime.h>
#include <mma.h>
#include <cstdint>
#include <cstddef>
using namespace nvcuda;

#define TS    512
#define BATCH 128
#define D     512
#define H     512
#define NG3   1536
#define MT    (TS*BATCH)
#define NGC   128
#define BH_   ((size_t)BATCH*H)
#define TBH_  ((size_t)TS*BATCH*H)
#define LDW   520

// smem float offsets
#define SM_W   0
#define SM_A   (48*LDW)                 // 24960
#define SM_O   (SM_A + 32*LDW)          // 41600
#define SM_WF  (SM_O + 2*32*48)         // 44672
#define SM_F   (SM_WF + 1024)           // 45696
#define SM_TOT (SM_F + 32)              // 45728 floats
#define REC_SMEM (SM_TOT*4)             // 182912 B

__device__ float    g_Gx[(size_t)MT*NG3];
__device__ float    g_Fx[(size_t)MT*2];
__device__ float    g_Wx[(size_t)NG3*D];
__device__ float    g_Whh[(size_t)NG3*H];
__device__ float    g_bias[NG3];
__device__ unsigned g_done4[TS*4];

__device__ __forceinline__ float t32(float x){ return wmma::__float_to_tf32(x); }
__device__ __forceinline__ float sigm(float x){ return 1.f/(1.f+expf(-x)); }

// ---------- prep: pack weights (tf32-rounded) + zero counters ----------
__global__ void prep_kernel(const float* __restrict__ Wi, const float* __restrict__ Wu,
                            const float* __restrict__ Wo, const float* __restrict__ bi,
                            const float* __restrict__ bu, const float* __restrict__ bo) {
    int n = blockIdx.x;
    if (n < NG3) {
        int g = n >> 9, j = n & 511;
        const float* W = (g==0) ? Wi : (g==1 ? Wu : Wo);
        const float* s = W + (size_t)j*(D+H);
        for (int k = threadIdx.x; k < D; k += blockDim.x) {
            g_Wx [(size_t)n*D + k] = t32(s[k]);
            g_Whh[(size_t)n*H + k] = t32(s[D+k]);
        }
        if (threadIdx.x == 0) g_bias[n] = (g==0 ? bi : (g==1 ? bu : bo))[j];
    } else {
        for (int k = threadIdx.x; k < TS*4; k += blockDim.x) g_done4[k] = 0u;
    }
}

// ---------- x-part of forget logits (fp32 exact) ----------
__global__ void fx_kernel(const float* __restrict__ X, const float* __restrict__ Wf,
                          const float* __restrict__ bf) {
    int m = blockIdx.x*8 + (threadIdx.x>>5);
    int lane = threadIdx.x & 31;
    const float* x = X + (size_t)m*D;
    float s0 = 0.f, s1 = 0.f;
    #pragma unroll 4
    for (int k = lane; k < D; k += 32) {
        float xv = x[k];
        s0 += xv * __ldg(&Wf[k]);
        s1 += xv * __ldg(&Wf[1024+k]);
    }
    #pragma unroll
    for (int o = 16; o; o >>= 1) {
        s0 += __shfl_xor_sync(~0u, s0, o);
        s1 += __shfl_xor_sync(~0u, s1, o);
    }
    if (lane == 0) {
        g_Fx[(size_t)m*2+0] = s0 + __ldg(&bf[0]);
        g_Fx[(size_t)m*2+1] = s1 + __ldg(&bf[1]);
    }
}

// ---------- big parallel GEMM: Gx = X @ Wx.T (tf32 WMMA) ----------
__global__ void __launch_bounds__(256) gemm_x(const float* __restrict__ X) {
    __shared__ float As[128*36];
    __shared__ float Bs[64*36];
    int tid = threadIdx.x, wid = tid>>5;
    int m0 = blockIdx.y*128, n0 = blockIdx.x*64;
    int wm = wid>>1, wn = wid&1;
    wmma::fragment<wmma::accumulator,16,16,8,float> acc[2][2];
    #pragma unroll
    for (int i=0;i<2;i++) { wmma::fill_fragment(acc[i][0],0.f); wmma::fill_fragment(acc[i][1],0.f); }

    for (int k0 = 0; k0 < D; k0 += 32) {
        #pragma unroll
        for (int u = 0; u < 4; u++) {
            int f4 = tid + u*256; int r = f4>>3, c4 = f4&7;
            float4 v = *(const float4*)(X + (size_t)(m0+r)*D + k0 + c4*4);
            float* d = &As[r*36 + c4*4];
            d[0]=t32(v.x); d[1]=t32(v.y); d[2]=t32(v.z); d[3]=t32(v.w);
        }
        #pragma unroll
        for (int u = 0; u < 2; u++) {
            int f4 = tid + u*256; int r = f4>>3, c4 = f4&7;
            float4 v = *(const float4*)(g_Wx + (size_t)(n0+r)*D + k0 + c4*4);
            float* d = &Bs[r*36 + c4*4];
            d[0]=v.x; d[1]=v.y; d[2]=v.z; d[3]=v.w;
        }
        __syncthreads();
        #pragma unroll
        for (int kk = 0; kk < 4; kk++) {
            wmma::fragment<wmma::matrix_a,16,16,8,wmma::precision::tf32,wmma::row_major> a0,a1;
            wmma::fragment<wmma::matrix_b,16,16,8,wmma::precision::tf32,wmma::col_major> b0,b1;
            wmma::load_matrix_sync(a0, &As[(wm*32+ 0)*36 + kk*8], 36);
            wmma::load_matrix_sync(a1, &As[(wm*32+16)*36 + kk*8], 36);
            wmma::load_matrix_sync(b0, &Bs[(wn*32+ 0)*36 + kk*8], 36);
            wmma::load_matrix_sync(b1, &Bs[(wn*32+16)*36 + kk*8], 36);
            wmma::mma_sync(acc[0][0], a0, b0, acc[0][0]);
            wmma::mma_sync(acc[0][1], a0, b1, acc[0][1]);
            wmma::mma_sync(acc[1][0], a1, b0, acc[1][0]);
            wmma::mma_sync(acc[1][1], a1, b1, acc[1][1]);
        }
        __syncthreads();
    }
    #pragma unroll
    for (int i=0;i<2;i++)
        #pragma unroll
        for (int j=0;j<2;j++)
            wmma::store_matrix_sync(g_Gx + (size_t)(m0+wm*32+i*16)*NG3 + n0+wn*32+j*16,
                                    acc[i][j], NG3, wmma::mem_row_major);
}

// ---------- persistent recurrent kernel: 128 CTAs, per-row-block sync ----------
__global__ void __launch_bounds__(256,1) rec_kernel(
        float* __restrict__ out, const float* __restrict__ Wf,
        const float* __restrict__ Ws1, const float* __restrict__ bs1,
        const float* __restrict__ Ws2, const float* __restrict__ bs2,
        long long out_size) {
    extern __shared__ float sm[];
    float* sW  = sm + SM_W;
    float* sA  = sm + SM_A;
    float* sO  = sm + SM_O;
    float* sWf = sm + SM_WF;
    float* sF  = sm + SM_F;
    int tid = threadIdx.x, wid = tid>>5, lane = tid&31;
    bool tail = out_size >= (long long)(TBH_ + 2*BH_);

    int rb = blockIdx.x >> 5, jt = blockIdx.x & 31;
    int row0 = rb*32, j0 = jt*16;

    // load recurrent weights (48 rows x 512) into smem, once
    for (int idx = tid; idx < 48*512; idx += 256) {
        int row = idx >> 9, k = idx & 511;
        sW[row*LDW + k] = g_Whh[(size_t)((row>>4)*512 + j0 + (row&15))*H + k];
    }
    // forget-gate h-part weights
    for (int k = tid; k < 512; k += 256) { sWf[k] = Wf[512+k]; sWf[512+k] = Wf[1536+k]; }

    // per-thread epilogue slots
    int p1 = tid + 256;
    int r0p = tid>>4, j0p = tid&15, r1p = p1>>4, j1p = p1&15;
    int b0 = row0+r0p, b1 = row0+r1p;
    int jj0 = j0+j0p, jj1 = j0+j1p;
    float bi0 = g_bias[jj0], bu0 = g_bias[512+jj0], bo0 = g_bias[1024+jj0];
    float bi1 = g_bias[jj1], bu1 = g_bias[512+jj1], bo1 = g_bias[1024+jj1];
    float c0 = 0.f, c1 = 0.f;

    // GEMM warp roles (warps 0..5): col-tile wc in {0,1,2}, K-half kh in {0,1}
    int wc = wid >> 1, kh = wid & 1;
    // f warp roles (warps 6,7): lane -> (row, logit)
    int fr = (lane & 15) + (wid - 6)*16;   // 0..31 (valid when wid>=6)
    int lg = lane >> 4;                    // 0 or 1
    float w1v[8], vb1[4], w2d[4], db = 0.f;
    if (wid >= 6) {
        #pragma unroll
        for (int i=0;i<8;i++) w1v[i] = Ws1[i];
        #pragma unroll
        for (int i=0;i<4;i++) { vb1[i] = bs1[i]; w2d[i] = Ws2[i] - Ws2[4+i]; }
        db = bs2[0] - bs2[1];
    }
    __syncthreads();

    for (int t = 0; t < TS; t++) {
        // prefetch x-part preactivations (independent of recurrence)
        size_t gb0 = ((size_t)t*BATCH + b0)*NG3, gb1 = ((size_t)t*BATCH + b1)*NG3;
        float gi0 = __ldg(&g_Gx[gb0+jj0]),      gi1 = __ldg(&g_Gx[gb1+jj1]);
        float gu0 = __ldg(&g_Gx[gb0+512+jj0]),  gu1 = __ldg(&g_Gx[gb1+512+jj1]);
        float go0 = __ldg(&g_Gx[gb0+1024+jj0]), go1 = __ldg(&g_Gx[gb1+1024+jj1]);
        float fxv = 0.f;
        if (wid >= 6) fxv = __ldg(&g_Fx[((size_t)t*BATCH + row0 + fr)*2 + lg]);

        if (t > 0) {
            if (tid == 0) { volatile unsigned* p = &g_done4[((t-1)<<2)|rb]; while (*p < 32u) {} }
            __syncthreads();
            // stage h[t-1] rows (tf32-rounded) for the GEMM
            const float* hb = out + (size_t)(t-1)*BH_;
            #pragma unroll 4
            for (int u = 0; u < 16; u++) {
                int f4 = tid + u*256;
                int r = f4 >> 7, c4 = f4 & 127;
                float4 v = *(const float4*)(hb + (size_t)(row0+r)*H + c4*4);
                float* d = &sA[r*LDW + c4*4];
                d[0]=t32(v.x); d[1]=t32(v.y); d[2]=t32(v.z); d[3]=t32(v.w);
            }
        }
        __syncthreads();

        if (wid < 6) {
            // gate GEMM: 32 rows x 48 cols, this warp: cols [wc*16,wc*16+16), K-half kh
            wmma::fragment<wmma::accumulator,16,16,8,float> acc0, acc1;
            wmma::fill_fragment(acc0, 0.f);
            wmma::fill_fragment(acc1, 0.f);
            if (t > 0) {
                int kk0 = kh*32;
                #pragma unroll 4
                for (int kk = kk0; kk < kk0+32; kk++) {
                    wmma::fragment<wmma::matrix_a,16,16,8,wmma::precision::tf32,wmma::row_major> a0, a1;
                    wmma::fragment<wmma::matrix_b,16,16,8,wmma::precision::tf32,wmma::col_major> bf;
                    wmma::load_matrix_sync(a0, &sA[kk*8], LDW);
                    wmma::load_matrix_sync(a1, &sA[16*LDW + kk*8], LDW);
                    wmma::load_matrix_sync(bf, &sW[(wc*16)*LDW + kk*8], LDW);
                    wmma::mma_sync(acc0, a0, bf, acc0);
                    wmma::mma_sync(acc1, a1, bf, acc1);
                }
            }
            wmma::store_matrix_sync(&sO[kh*1536 + wc*16],          acc0, 48, wmma::mem_row_major);
            wmma::store_matrix_sync(&sO[kh*1536 + 16*48 + wc*16],  acc1, 48, wmma::mem_row_major);
        } else {
            // forget gate for this CTA's 32 rows (fp32-exact h from global)
            float s = 0.f, s2 = 0.f;
            if (t > 0) {
                const float4* hr = (const float4*)(out + (size_t)(t-1)*BH_ + (size_t)(row0+fr)*H);
                const float4* wr = (const float4*)(sWf + lg*512);
                #pragma unroll 8
                for (int k4 = 0; k4 < 128; k4 += 2) {
                    float4 a = hr[k4],   b = wr[k4];
                    s  += a.x*b.x + a.y*b.y + a.z*b.z + a.w*b.w;
                    float4 a2 = hr[k4+1], b2 = wr[k4+1];
                    s2 += a2.x*b2.x + a2.y*b2.y + a2.z*b2.z + a2.w*b2.w;
                }
            }
            s += s2 + fxv;
            float other = __shfl_xor_sync(~0u, s, 16);
            if (lg == 0) {
                float fl0 = s, fl1 = other;
                float h0 = tanhf(w1v[0]*fl0 + w1v[1]*fl1 + vb1[0]);
                float h1 = tanhf(w1v[2]*fl0 + w1v[3]*fl1 + vb1[1]);
                float h2 = tanhf(w1v[4]*fl0 + w1v[5]*fl1 + vb1[2]);
                float h3 = tanhf(w1v[6]*fl0 + w1v[7]*fl1 + vb1[3]);
                float dl = w2d[0]*h0 + w2d[1]*h1 + w2d[2]*h2 + w2d[3]*h3 + db;
                sF[fr] = sigm(dl);
            }
        }
        __syncthreads();

        // epilogue: combine K-halves, x-part, bias; LSTM cell update
        float f0 = sF[r0p], f1 = sF[r1p];
        float pi0 = sO[r0p*48 + j0p]      + sO[1536 + r0p*48 + j0p]      + gi0 + bi0;
        float pu0 = sO[r0p*48 + 16 + j0p] + sO[1536 + r0p*48 + 16 + j0p] + gu0 + bu0;
        float po0 = sO[r0p*48 + 32 + j0p] + sO[1536 + r0p*48 + 32 + j0p] + go0 + bo0;
        float pi1 = sO[r1p*48 + j1p]      + sO[1536 + r1p*48 + j1p]      + gi1 + bi1;
        float pu1 = sO[r1p*48 + 16 + j1p] + sO[1536 + r1p*48 + 16 + j1p] + gu1 + bu1;
        float po1 = sO[r1p*48 + 32 + j1p] + sO[1536 + r1p*48 + 32 + j1p] + go1 + bo1;
        c0 = f0*c0 + sigm(pi0)*tanhf(pu0);
        c1 = f1*c1 + sigm(pi1)*tanhf(pu1);
        float h0 = sigm(po0)*tanhf(c0);
        float h1 = sigm(po1)*tanhf(c1);
        out[(size_t)t*BH_ + (size_t)b0*H + jj0] = h0;
        out[(size_t)t*BH_ + (size_t)b1*H + jj1] = h1;
        if (t == TS-1 && tail) {
            out[TBH_ + (size_t)b0*H + jj0] = h0;
            out[TBH_ + (size_t)b1*H + jj1] = h1;
            out[TBH_ + BH_ + (size_t)b0*H + jj0] = c0;
            out[TBH_ + BH_ + (size_t)b1*H + jj1] = c1;
        }
        __syncthreads();
        if (tid == 0) { __threadfence(); atomicAdd(&g_done4[(t<<2)|rb], 1u); }
    }
}

extern "C" void kernel_launch(void* const* d_in, const int* in_sizes, int n_in,
                              void* d_out, int out_size) {
    const float* X   = (const float*)d_in[0];
    const float* Wf  = (const float*)d_in[1];
    const float* bf  = (const float*)d_in[2];
    const float* Wi  = (const float*)d_in[3];
    const float* bi  = (const float*)d_in[4];
    const float* Wu  = (const float*)d_in[5];
    const float* bu  = (const float*)d_in[6];
    const float* Wo  = (const float*)d_in[7];
    const float* bo  = (const float*)d_in[8];
    const float* Ws1 = (const float*)d_in[9];
    const float* bs1 = (const float*)d_in[10];
    const float* Ws2 = (const float*)d_in[11];
    const float* bs2 = (const float*)d_in[12];
    float* out = (float*)d_out;

    cudaFuncSetAttribute(rec_kernel, cudaFuncAttributeMaxDynamicSharedMemorySize, REC_SMEM);

    prep_kernel<<<NG3+1, 128>>>(Wi, Wu, Wo, bi, bu, bo);
    fx_kernel<<<MT/8, 256>>>(X, Wf, bf);
    dim3 g(NG3/64, MT/128);
    gemm_x<<<g, 256>>>(X);
    rec_kernel<<<NGC, 256, REC_SMEM>>>(out, Wf, Ws1, bs1, Ws2, bs2, (long long)out_size);
}

// round 6
// speedup vs baseline: 2.1964x; 1.1704x over previous
#include <cuda_runtime.h>
#include <mma.h>
#include <cstdint>
#include <cstddef>
using namespace nvcuda;

#define TS    512
#define BATCH 128
#define D     512
#define H     512
#define NG3   1536
#define MT    (TS*BATCH)
#define NGC   128
#define BH_   ((size_t)BATCH*H)
#define TBH_  ((size_t)TS*BATCH*H)
#define LDW   516

// smem float offsets (rec kernel)
#define SM_W   0
#define SM_A   (48*LDW)                  // 24768
#define SM_O   (SM_A + 32*LDW)           // 41280
#define SM_WF  (SM_O + 2*32*48)          // 44352
#define SM_F   (SM_WF + 1024)            // 45376
#define SM_FL  (SM_F + 32)               // 45408
#define SM_TOT (SM_FL + 64)              // 45472 floats
#define REC_SMEM (SM_TOT*4)              // 181888 B

__device__ float    g_Gx[(size_t)MT*NG3];
__device__ float    g_Fx[(size_t)MT*2];
__device__ float    g_Wx[(size_t)NG3*D];
__device__ float    g_Whh[(size_t)NG3*H];
__device__ float    g_bias[NG3];
__device__ unsigned g_flagw[(size_t)TS*NGC];

__device__ __forceinline__ float t32(float x){ return wmma::__float_to_tf32(x); }
__device__ __forceinline__ float sigm(float x){ return 1.f/(1.f+expf(-x)); }

// ---------- prep: pack weights (tf32-rounded) + zero flags ----------
__global__ void prep_kernel(const float* __restrict__ Wi, const float* __restrict__ Wu,
                            const float* __restrict__ Wo, const float* __restrict__ bi,
                            const float* __restrict__ bu, const float* __restrict__ bo) {
    int n = blockIdx.x;
    if (n < NG3) {
        int g = n >> 9, j = n & 511;
        const float* W = (g==0) ? Wi : (g==1 ? Wu : Wo);
        const float* s = W + (size_t)j*(D+H);
        for (int k = threadIdx.x; k < D; k += blockDim.x) {
            g_Wx [(size_t)n*D + k] = t32(s[k]);
            g_Whh[(size_t)n*H + k] = t32(s[D+k]);
        }
        if (threadIdx.x == 0) g_bias[n] = (g==0 ? bi : (g==1 ? bu : bo))[j];
    } else {
        int base = (n - NG3) * 8192;
        for (int k = threadIdx.x; k < 8192; k += blockDim.x) g_flagw[base + k] = 0u;
    }
}

// ---------- x-part of forget logits (fp32 exact) ----------
__global__ void fx_kernel(const float* __restrict__ X, const float* __restrict__ Wf,
                          const float* __restrict__ bf) {
    int m = blockIdx.x*8 + (threadIdx.x>>5);
    int lane = threadIdx.x & 31;
    const float* x = X + (size_t)m*D;
    float s0 = 0.f, s1 = 0.f;
    #pragma unroll 4
    for (int k = lane; k < D; k += 32) {
        float xv = x[k];
        s0 += xv * __ldg(&Wf[k]);
        s1 += xv * __ldg(&Wf[1024+k]);
    }
    #pragma unroll
    for (int o = 16; o; o >>= 1) {
        s0 += __shfl_xor_sync(~0u, s0, o);
        s1 += __shfl_xor_sync(~0u, s1, o);
    }
    if (lane == 0) {
        g_Fx[(size_t)m*2+0] = s0 + __ldg(&bf[0]);
        g_Fx[(size_t)m*2+1] = s1 + __ldg(&bf[1]);
    }
}

// ---------- big parallel GEMM: Gx = X @ Wx.T (tf32 WMMA, 128x128 tiles) ----------
__global__ void __launch_bounds__(256) gemm_x(const float* __restrict__ X) {
    __shared__ float As[128*36];
    __shared__ float Bs[128*36];
    int tid = threadIdx.x, wid = tid>>5;
    int n0 = blockIdx.x*128, m0 = blockIdx.y*128;
    int wm = wid>>1, wn = wid&1;
    wmma::fragment<wmma::accumulator,16,16,8,float> acc[2][4];
    #pragma unroll
    for (int i=0;i<2;i++)
        #pragma unroll
        for (int j=0;j<4;j++) wmma::fill_fragment(acc[i][j], 0.f);

    for (int k0 = 0; k0 < D; k0 += 32) {
        #pragma unroll
        for (int u = 0; u < 4; u++) {
            int f4 = tid + u*256; int r = f4>>3, c4 = f4&7;
            float4 v = *(const float4*)(X + (size_t)(m0+r)*D + k0 + c4*4);
            float* d = &As[r*36 + c4*4];
            d[0]=t32(v.x); d[1]=t32(v.y); d[2]=t32(v.z); d[3]=t32(v.w);
        }
        #pragma unroll
        for (int u = 0; u < 4; u++) {
            int f4 = tid + u*256; int r = f4>>3, c4 = f4&7;
            float4 v = *(const float4*)(g_Wx + (size_t)(n0+r)*D + k0 + c4*4);
            float* d = &Bs[r*36 + c4*4];
            d[0]=v.x; d[1]=v.y; d[2]=v.z; d[3]=v.w;
        }
        __syncthreads();
        #pragma unroll
        for (int kk = 0; kk < 4; kk++) {
            wmma::fragment<wmma::matrix_a,16,16,8,wmma::precision::tf32,wmma::row_major> a0,a1;
            wmma::fragment<wmma::matrix_b,16,16,8,wmma::precision::tf32,wmma::col_major> b0,b1,b2,b3;
            wmma::load_matrix_sync(a0, &As[(wm*32+ 0)*36 + kk*8], 36);
            wmma::load_matrix_sync(a1, &As[(wm*32+16)*36 + kk*8], 36);
            wmma::load_matrix_sync(b0, &Bs[(wn*64+ 0)*36 + kk*8], 36);
            wmma::load_matrix_sync(b1, &Bs[(wn*64+16)*36 + kk*8], 36);
            wmma::load_matrix_sync(b2, &Bs[(wn*64+32)*36 + kk*8], 36);
            wmma::load_matrix_sync(b3, &Bs[(wn*64+48)*36 + kk*8], 36);
            wmma::mma_sync(acc[0][0], a0, b0, acc[0][0]);
            wmma::mma_sync(acc[0][1], a0, b1, acc[0][1]);
            wmma::mma_sync(acc[0][2], a0, b2, acc[0][2]);
            wmma::mma_sync(acc[0][3], a0, b3, acc[0][3]);
            wmma::mma_sync(acc[1][0], a1, b0, acc[1][0]);
            wmma::mma_sync(acc[1][1], a1, b1, acc[1][1]);
            wmma::mma_sync(acc[1][2], a1, b2, acc[1][2]);
            wmma::mma_sync(acc[1][3], a1, b3, acc[1][3]);
        }
        __syncthreads();
    }
    #pragma unroll
    for (int i=0;i<2;i++)
        #pragma unroll
        for (int j=0;j<4;j++)
            wmma::store_matrix_sync(g_Gx + (size_t)(m0+wm*32+i*16)*NG3 + n0+wn*64+j*16,
                                    acc[i][j], NG3, wmma::mem_row_major);
}

// ---------- persistent recurrent kernel ----------
__global__ void __launch_bounds__(256,1) rec_kernel(
        float* __restrict__ out, const float* __restrict__ Wf,
        const float* __restrict__ Ws1, const float* __restrict__ bs1,
        const float* __restrict__ Ws2, const float* __restrict__ bs2,
        long long out_size) {
    extern __shared__ float sm[];
    float* sW  = sm + SM_W;
    float* sA  = sm + SM_A;
    float* sO  = sm + SM_O;
    float* sWf = sm + SM_WF;
    float* sF  = sm + SM_F;
    float* sFL = sm + SM_FL;     // [2][32] logits
    int tid = threadIdx.x, wid = tid>>5, lane = tid&31;
    bool tail = out_size >= (long long)(TBH_ + 2*BH_);

    int rb = blockIdx.x >> 5, jt = blockIdx.x & 31;
    int row0 = rb*32, j0 = jt*16;

    // recurrent weights (48 rows x 512) -> smem, once
    for (int idx = tid; idx < 48*512; idx += 256) {
        int row = idx >> 9, k = idx & 511;
        sW[row*LDW + k] = g_Whh[(size_t)((row>>4)*512 + j0 + (row&15))*H + k];
    }
    // forget-gate h-part weights
    for (int k = tid; k < 512; k += 256) { sWf[k] = Wf[512+k]; sWf[512+k] = Wf[1536+k]; }

    // epilogue slots
    int p1 = tid + 256;
    int r0p = tid>>4, j0p = tid&15, r1p = p1>>4, j1p = p1&15;
    int b0 = row0+r0p, b1 = row0+r1p;
    int jj0 = j0+j0p, jj1 = j0+j1p;
    float bi0 = g_bias[jj0], bu0 = g_bias[512+jj0], bo0 = g_bias[1024+jj0];
    float bi1 = g_bias[jj1], bu1 = g_bias[512+jj1], bo1 = g_bias[1024+jj1];
    float c0 = 0.f, c1 = 0.f;

    // GEMM warp roles (0..5): col-tile wc {0,1,2}, K-half kh {0,1}
    int wc = wid >> 1, kh = wid & 1;
    // f warps (6,7): warp 6 -> logit0, warp 7 -> logit1; lane owns row=lane
    int lg = wid - 6;  // valid for wid>=6
    float w1v[8], vb1[4], w2d[4], db = 0.f;
    if (wid == 6) {
        #pragma unroll
        for (int i=0;i<8;i++) w1v[i] = Ws1[i];
        #pragma unroll
        for (int i=0;i<4;i++) { vb1[i] = bs1[i]; w2d[i] = Ws2[i] - Ws2[4+i]; }
        db = bs2[0] - bs2[1];
    }
    __syncthreads();

    for (int t = 0; t < TS; t++) {
        // prefetch x-part preactivations (no recurrent dependency)
        size_t gb0 = ((size_t)t*BATCH + b0)*NG3, gb1 = ((size_t)t*BATCH + b1)*NG3;
        float gi0 = __ldg(&g_Gx[gb0+jj0]),      gi1 = __ldg(&g_Gx[gb1+jj1]);
        float gu0 = __ldg(&g_Gx[gb0+512+jj0]),  gu1 = __ldg(&g_Gx[gb1+512+jj1]);
        float go0 = __ldg(&g_Gx[gb0+1024+jj0]), go1 = __ldg(&g_Gx[gb1+1024+jj1]);
        float fxv = 0.f;
        if (wid >= 6) fxv = __ldg(&g_Fx[((size_t)t*BATCH + row0 + lane)*2 + lg]);

        if (t > 0) {
            if (wid == 0) {
                volatile unsigned* fp = &g_flagw[(size_t)(t-1)*NGC + rb*32 + lane];
                while (*fp == 0u) {}
            }
            __syncthreads();
            // stage h[t-1] rows (tf32-rounded)
            const float* hb = out + (size_t)(t-1)*BH_;
            #pragma unroll 4
            for (int u = 0; u < 16; u++) {
                int f4 = tid + u*256;
                int r = f4 >> 7, c4 = f4 & 127;
                float4 v = *(const float4*)(hb + (size_t)(row0+r)*H + c4*4);
                float* d = &sA[r*LDW + c4*4];
                d[0]=t32(v.x); d[1]=t32(v.y); d[2]=t32(v.z); d[3]=t32(v.w);
            }
        }
        __syncthreads();

        if (wid < 6) {
            wmma::fragment<wmma::accumulator,16,16,8,float> acc0, acc1;
            wmma::fill_fragment(acc0, 0.f);
            wmma::fill_fragment(acc1, 0.f);
            if (t > 0) {
                int kk0 = kh*32;
                #pragma unroll 4
                for (int kk = kk0; kk < kk0+32; kk++) {
                    wmma::fragment<wmma::matrix_a,16,16,8,wmma::precision::tf32,wmma::row_major> a0, a1;
                    wmma::fragment<wmma::matrix_b,16,16,8,wmma::precision::tf32,wmma::col_major> bf;
                    wmma::load_matrix_sync(a0, &sA[kk*8], LDW);
                    wmma::load_matrix_sync(a1, &sA[16*LDW + kk*8], LDW);
                    wmma::load_matrix_sync(bf, &sW[(wc*16)*LDW + kk*8], LDW);
                    wmma::mma_sync(acc0, a0, bf, acc0);
                    wmma::mma_sync(acc1, a1, bf, acc1);
                }
            }
            wmma::store_matrix_sync(&sO[kh*1536 + wc*16],          acc0, 48, wmma::mem_row_major);
            wmma::store_matrix_sync(&sO[kh*1536 + 16*48 + wc*16],  acc1, 48, wmma::mem_row_major);
        } else {
            // f logits from staged sA (lane owns row=lane, warp owns logit lg)
            float s = 0.f;
            if (t > 0) {
                const float4* ar = (const float4*)(sA + lane*LDW);
                const float4* wr = (const float4*)(sWf + lg*512);
                float s2 = 0.f;
                #pragma unroll 8
                for (int k4 = 0; k4 < 128; k4 += 2) {
                    float4 a = ar[k4],   b = wr[k4];
                    s  += a.x*b.x + a.y*b.y + a.z*b.z + a.w*b.w;
                    float4 a2 = ar[k4+1], b2 = wr[k4+1];
                    s2 += a2.x*b2.x + a2.y*b2.y + a2.z*b2.z + a2.w*b2.w;
                }
                s += s2;
            }
            sFL[lg*32 + lane] = s + fxv;
            asm volatile("bar.sync 1, 64;" ::: "memory");
            if (wid == 6) {
                float fl0 = sFL[lane], fl1 = sFL[32 + lane];
                float h0 = tanhf(w1v[0]*fl0 + w1v[1]*fl1 + vb1[0]);
                float h1 = tanhf(w1v[2]*fl0 + w1v[3]*fl1 + vb1[1]);
                float h2 = tanhf(w1v[4]*fl0 + w1v[5]*fl1 + vb1[2]);
                float h3 = tanhf(w1v[6]*fl0 + w1v[7]*fl1 + vb1[3]);
                float dl = w2d[0]*h0 + w2d[1]*h1 + w2d[2]*h2 + w2d[3]*h3 + db;
                sF[lane] = sigm(dl);
            }
        }
        __syncthreads();

        // epilogue: combine K-halves + x-part + bias; LSTM update
        float f0 = sF[r0p], f1 = sF[r1p];
        float pi0 = sO[r0p*48 + j0p]      + sO[1536 + r0p*48 + j0p]      + gi0 + bi0;
        float pu0 = sO[r0p*48 + 16 + j0p] + sO[1536 + r0p*48 + 16 + j0p] + gu0 + bu0;
        float po0 = sO[r0p*48 + 32 + j0p] + sO[1536 + r0p*48 + 32 + j0p] + go0 + bo0;
        float pi1 = sO[r1p*48 + j1p]      + sO[1536 + r1p*48 + j1p]      + gi1 + bi1;
        float pu1 = sO[r1p*48 + 16 + j1p] + sO[1536 + r1p*48 + 16 + j1p] + gu1 + bu1;
        float po1 = sO[r1p*48 + 32 + j1p] + sO[1536 + r1p*48 + 32 + j1p] + go1 + bo1;
        c0 = f0*c0 + sigm(pi0)*tanhf(pu0);
        c1 = f1*c1 + sigm(pi1)*tanhf(pu1);
        float h0 = sigm(po0)*tanhf(c0);
        float h1 = sigm(po1)*tanhf(c1);
        out[(size_t)t*BH_ + (size_t)b0*H + jj0] = h0;
        out[(size_t)t*BH_ + (size_t)b1*H + jj1] = h1;
        if (t == TS-1 && tail) {
            out[TBH_ + (size_t)b0*H + jj0] = h0;
            out[TBH_ + (size_t)b1*H + jj1] = h1;
            out[TBH_ + BH_ + (size_t)b0*H + jj0] = c0;
            out[TBH_ + BH_ + (size_t)b1*H + jj1] = c1;
        }
        __syncthreads();
        if (tid == 0) {
            __threadfence();
            *(volatile unsigned*)&g_flagw[(size_t)t*NGC + blockIdx.x] = 1u;
        }
    }
}

extern "C" void kernel_launch(void* const* d_in, const int* in_sizes, int n_in,
                              void* d_out, int out_size) {
    const float* X   = (const float*)d_in[0];
    const float* Wf  = (const float*)d_in[1];
    const float* bf  = (const float*)d_in[2];
    const float* Wi  = (const float*)d_in[3];
    const float* bi  = (const float*)d_in[4];
    const float* Wu  = (const float*)d_in[5];
    const float* bu  = (const float*)d_in[6];
    const float* Wo  = (const float*)d_in[7];
    const float* bo  = (const float*)d_in[8];
    const float* Ws1 = (const float*)d_in[9];
    const float* bs1 = (const float*)d_in[10];
    const float* Ws2 = (const float*)d_in[11];
    const float* bs2 = (const float*)d_in[12];
    float* out = (float*)d_out;

    cudaFuncSetAttribute(rec_kernel, cudaFuncAttributeMaxDynamicSharedMemorySize, REC_SMEM);

    prep_kernel<<<NG3+8, 128>>>(Wi, Wu, Wo, bi, bu, bo);
    fx_kernel<<<MT/8, 256>>>(X, Wf, bf);
    dim3 g(NG3/128, MT/128);
    gemm_x<<<g, 256>>>(X);
    rec_kernel<<<NGC, 256, REC_SMEM>>>(out, Wf, Ws1, bs1, Ws2, bs2, (long long)out_size);
}

// round 7
// speedup vs baseline: 2.5648x; 1.1677x over previous
#include <cuda_runtime.h>
#include <mma.h>
#include <cstdint>
#include <cstddef>
using namespace nvcuda;

#define TS    512
#define BATCH 128
#define D     512
#define H     512
#define NG3   1536
#define MT    (TS*BATCH)
#define NGC   128
#define BH_   ((size_t)BATCH*H)
#define TBH_  ((size_t)TS*BATCH*H)
#define LDW   516
#define LDO   52

// rec smem float offsets
#define SM_W   0
#define SM_A   (48*LDW)                 // 24768
#define SM_O   (SM_A + 32*LDW)          // 41280
#define SM_F   (SM_O + 4*32*LDO)        // 47936
#define SM_TOT (SM_F + 32)              // 47968
#define REC_SMEM (SM_TOT*4)             // 191872 B

// gemm_x smem: 3 stages x (256 rows x 36 floats)
#define GXS        3
#define GX_STAGE_F (256*36)
#define GX_SMEM    (GXS*GX_STAGE_F*4)   // 110592 B

__device__ float    g_Gx[(size_t)MT*NG3];
__device__ float    g_Fx[(size_t)MT*2];
__device__ float    g_Xr[(size_t)MT*D];
__device__ float    g_Wx[(size_t)NG3*D];
__device__ float    g_Whh[(size_t)NG3*H];
__device__ float    g_bias[NG3];
__device__ unsigned g_flagw[(size_t)TS*NGC];

__device__ __forceinline__ float t32(float x){ return wmma::__float_to_tf32(x); }
__device__ __forceinline__ float sigm(float x){ return 1.f/(1.f+expf(-x)); }
__device__ __forceinline__ void cpa16(uint32_t dst, const void* src){
    asm volatile("cp.async.ca.shared.global [%0], [%1], 16;\n" :: "r"(dst), "l"(src));
}

// ---------- prep: pack weights (tf32-rounded) + zero flags ----------
__global__ void prep_kernel(const float* __restrict__ Wi, const float* __restrict__ Wu,
                            const float* __restrict__ Wo, const float* __restrict__ bi,
                            const float* __restrict__ bu, const float* __restrict__ bo) {
    int n = blockIdx.x;
    if (n < NG3) {
        int g = n >> 9, j = n & 511;
        const float* W = (g==0) ? Wi : (g==1 ? Wu : Wo);
        const float* s = W + (size_t)j*(D+H);
        for (int k = threadIdx.x; k < D; k += blockDim.x) {
            g_Wx [(size_t)n*D + k] = t32(s[k]);
            g_Whh[(size_t)n*H + k] = t32(s[D+k]);
        }
        if (threadIdx.x == 0) g_bias[n] = (g==0 ? bi : (g==1 ? bu : bo))[j];
    } else {
        int base = (n - NG3) * 8192;
        for (int k = threadIdx.x; k < 8192; k += blockDim.x) g_flagw[base + k] = 0u;
    }
}

// ---------- round X to tf32 once ----------
__global__ void prepx_kernel(const float* __restrict__ X) {
    size_t i = ((size_t)blockIdx.x*256 + threadIdx.x)*4;
    float4 v = *(const float4*)(X + i);
    float4 o; o.x=t32(v.x); o.y=t32(v.y); o.z=t32(v.z); o.w=t32(v.w);
    *(float4*)(g_Xr + i) = o;
}

// ---------- x-part of forget logits (fp32 exact) ----------
__global__ void fx_kernel(const float* __restrict__ X, const float* __restrict__ Wf,
                          const float* __restrict__ bf) {
    int m = blockIdx.x*8 + (threadIdx.x>>5);
    int lane = threadIdx.x & 31;
    const float* x = X + (size_t)m*D;
    float s0 = 0.f, s1 = 0.f;
    #pragma unroll 4
    for (int k = lane; k < D; k += 32) {
        float xv = x[k];
        s0 += xv * __ldg(&Wf[k]);
        s1 += xv * __ldg(&Wf[1024+k]);
    }
    #pragma unroll
    for (int o = 16; o; o >>= 1) {
        s0 += __shfl_xor_sync(~0u, s0, o);
        s1 += __shfl_xor_sync(~0u, s1, o);
    }
    if (lane == 0) {
        g_Fx[(size_t)m*2+0] = s0 + __ldg(&bf[0]);
        g_Fx[(size_t)m*2+1] = s1 + __ldg(&bf[1]);
    }
}

// ---------- big parallel GEMM: Gx = Xr @ Wx.T (tf32 WMMA, cp.async pipeline) ----------
__global__ void __launch_bounds__(256) gemm_x() {
    extern __shared__ float sb[];
    uint32_t sbase = (uint32_t)__cvta_generic_to_shared(sb);
    int tid = threadIdx.x, wid = tid>>5;
    int n0 = blockIdx.x*128, m0 = blockIdx.y*128;
    int wm = wid>>1, wn = wid&1;
    int lr = tid>>3, lc = (tid&7)*4;

    wmma::fragment<wmma::accumulator,16,16,8,float> acc[2][4];
    #pragma unroll
    for (int i=0;i<2;i++)
        #pragma unroll
        for (int j=0;j<4;j++) wmma::fill_fragment(acc[i][j], 0.f);

    auto load_chunk = [&](int s, int kc) {
        const float* As = g_Xr + (size_t)m0*D + kc*32;
        const float* Bsrc = g_Wx + (size_t)n0*D + kc*32;
        uint32_t ds = sbase + (uint32_t)s*GX_STAGE_F*4;
        #pragma unroll
        for (int u = 0; u < 4; u++) {
            int rr = lr + u*32;
            cpa16(ds + (uint32_t)(rr*36+lc)*4,       As   + (size_t)rr*D + lc);
            cpa16(ds + (uint32_t)((128+rr)*36+lc)*4, Bsrc + (size_t)rr*D + lc);
        }
        asm volatile("cp.async.commit_group;\n");
    };

    load_chunk(0,0); load_chunk(1,1);
    for (int kc = 0; kc < 16; kc++) {
        asm volatile("cp.async.wait_group 1;\n");
        __syncthreads();
        if (kc+2 < 16) load_chunk((kc+2)%GXS, kc+2);
        else asm volatile("cp.async.commit_group;\n");
        float* As = sb + (kc%GXS)*GX_STAGE_F;
        float* Bs = As + 128*36;
        #pragma unroll
        for (int kk = 0; kk < 4; kk++) {
            wmma::fragment<wmma::matrix_a,16,16,8,wmma::precision::tf32,wmma::row_major> a0,a1;
            wmma::fragment<wmma::matrix_b,16,16,8,wmma::precision::tf32,wmma::col_major> b0,b1,b2,b3;
            wmma::load_matrix_sync(a0, &As[(wm*32+ 0)*36 + kk*8], 36);
            wmma::load_matrix_sync(a1, &As[(wm*32+16)*36 + kk*8], 36);
            wmma::load_matrix_sync(b0, &Bs[(wn*64+ 0)*36 + kk*8], 36);
            wmma::load_matrix_sync(b1, &Bs[(wn*64+16)*36 + kk*8], 36);
            wmma::load_matrix_sync(b2, &Bs[(wn*64+32)*36 + kk*8], 36);
            wmma::load_matrix_sync(b3, &Bs[(wn*64+48)*36 + kk*8], 36);
            wmma::mma_sync(acc[0][0], a0, b0, acc[0][0]);
            wmma::mma_sync(acc[0][1], a0, b1, acc[0][1]);
            wmma::mma_sync(acc[0][2], a0, b2, acc[0][2]);
            wmma::mma_sync(acc[0][3], a0, b3, acc[0][3]);
            wmma::mma_sync(acc[1][0], a1, b0, acc[1][0]);
            wmma::mma_sync(acc[1][1], a1, b1, acc[1][1]);
            wmma::mma_sync(acc[1][2], a1, b2, acc[1][2]);
            wmma::mma_sync(acc[1][3], a1, b3, acc[1][3]);
        }
    }
    #pragma unroll
    for (int i=0;i<2;i++)
        #pragma unroll
        for (int j=0;j<4;j++)
            wmma::store_matrix_sync(g_Gx + (size_t)(m0+wm*32+i*16)*NG3 + n0+wn*64+j*16,
                                    acc[i][j], NG3, wmma::mem_row_major);
}

// ---------- persistent recurrent kernel: 128 CTAs x 512 threads ----------
__global__ void __launch_bounds__(512,1) rec_kernel(
        float* __restrict__ out, const float* __restrict__ Wf,
        const float* __restrict__ Ws1, const float* __restrict__ bs1,
        const float* __restrict__ Ws2, const float* __restrict__ bs2,
        long long out_size) {
    extern __shared__ float sm[];
    float* sW = sm + SM_W;
    float* sA = sm + SM_A;
    float* sO = sm + SM_O;
    float* sF = sm + SM_F;
    int tid = threadIdx.x, wid = tid>>5, lane = tid&31;
    bool tail = out_size >= (long long)(TBH_ + 2*BH_);

    int rb = blockIdx.x >> 5, jt = blockIdx.x & 31;
    int row0 = rb*32, j0 = jt*16;

    // recurrent weights (48 rows x 512) -> smem, once
    for (int idx = tid; idx < 48*512; idx += 512) {
        int row = idx >> 9, k = idx & 511;
        sW[row*LDW + k] = g_Whh[(size_t)((row>>4)*512 + j0 + (row&15))*H + k];
    }

    // epilogue slot: 1 output per thread
    int rp = tid>>4, jp = tid&15;
    int bq = row0+rp, jj = j0+jp;
    float bI = g_bias[jj], bU = g_bias[512+jj], bO = g_bias[1024+jj];
    float cst = 0.f;

    // GEMM roles: warps 0..11 -> wc (gate) in {0,1,2}, kq in {0..3}
    int wc = wid >> 2, kq = wid & 3;
    // f roles: warps 12..15 -> 8 rows each; per-lane weight slices in regs
    int fw = wid - 12, rbase = fw*8;
    float wA[16], wB[16];
    float w1v[8], vb1[4], w2d[4], db = 0.f;
    if (wid >= 12) {
        #pragma unroll
        for (int i = 0; i < 4; i++) {
            float4 a = *(const float4*)(Wf + 512  + i*128 + lane*4);
            float4 b = *(const float4*)(Wf + 1536 + i*128 + lane*4);
            wA[i*4]=a.x; wA[i*4+1]=a.y; wA[i*4+2]=a.z; wA[i*4+3]=a.w;
            wB[i*4]=b.x; wB[i*4+1]=b.y; wB[i*4+2]=b.z; wB[i*4+3]=b.w;
        }
        #pragma unroll
        for (int i=0;i<8;i++) w1v[i] = Ws1[i];
        #pragma unroll
        for (int i=0;i<4;i++) { vb1[i] = bs1[i]; w2d[i] = Ws2[i] - Ws2[4+i]; }
        db = bs2[0] - bs2[1];
    }
    __syncthreads();

    // preload B fragments into registers (persist across all 512 steps)
    wmma::fragment<wmma::matrix_b,16,16,8,wmma::precision::tf32,wmma::col_major> bfr[16];
    if (wid < 12) {
        #pragma unroll
        for (int q = 0; q < 16; q++)
            wmma::load_matrix_sync(bfr[q], &sW[(wc*16)*LDW + (kq*16+q)*8], LDW);
    }

    for (int t = 0; t < TS; t++) {
        // prefetch x-parts (no recurrent dependency)
        size_t gb = ((size_t)t*BATCH + bq)*NG3;
        float gi = __ldg(&g_Gx[gb+jj]);
        float gu = __ldg(&g_Gx[gb+512+jj]);
        float go = __ldg(&g_Gx[gb+1024+jj]);
        float fx0 = 0.f, fx1 = 0.f;
        if (wid >= 12 && lane < 8) {
            const float* fp = &g_Fx[((size_t)t*BATCH + row0 + rbase + lane)*2];
            fx0 = __ldg(fp); fx1 = __ldg(fp+1);
        }

        if (t > 0) {
            if (wid == 0) {
                volatile unsigned* fl = &g_flagw[(size_t)(t-1)*NGC + rb*32 + lane];
                while (*fl == 0u) {}
            }
            __syncthreads();
            // stage h[t-1] rows (tf32-rounded) for the GEMM
            const float* hb = out + (size_t)(t-1)*BH_;
            #pragma unroll
            for (int u = 0; u < 8; u++) {
                int f4 = tid + u*512;
                int r = f4 >> 7, c4 = f4 & 127;
                float4 v = *(const float4*)(hb + (size_t)(row0+r)*H + c4*4);
                float* d = &sA[r*LDW + c4*4];
                d[0]=t32(v.x); d[1]=t32(v.y); d[2]=t32(v.z); d[3]=t32(v.w);
            }
        }
        __syncthreads();

        if (wid < 12) {
            wmma::fragment<wmma::accumulator,16,16,8,float> acc0, acc1;
            wmma::fill_fragment(acc0, 0.f);
            wmma::fill_fragment(acc1, 0.f);
            if (t > 0) {
                #pragma unroll
                for (int q = 0; q < 16; q++) {
                    int kk = kq*16 + q;
                    wmma::fragment<wmma::matrix_a,16,16,8,wmma::precision::tf32,wmma::row_major> a0, a1;
                    wmma::load_matrix_sync(a0, &sA[kk*8], LDW);
                    wmma::load_matrix_sync(a1, &sA[16*LDW + kk*8], LDW);
                    wmma::mma_sync(acc0, a0, bfr[q], acc0);
                    wmma::mma_sync(acc1, a1, bfr[q], acc1);
                }
            }
            wmma::store_matrix_sync(&sO[(kq*32+ 0)*LDO + wc*16], acc0, LDO, wmma::mem_row_major);
            wmma::store_matrix_sync(&sO[(kq*32+16)*LDO + wc*16], acc1, LDO, wmma::mem_row_major);
        } else {
            // forget gate: 8 rows per warp, fp32 h from global (L2), weights in regs
            float p0[8], p1[8];
            #pragma unroll
            for (int r=0;r<8;r++){ p0[r]=0.f; p1[r]=0.f; }
            if (t > 0) {
                const float* hb = out + (size_t)(t-1)*BH_ + (size_t)(row0+rbase)*H;
                #pragma unroll
                for (int r = 0; r < 8; r++) {
                    float s0=0.f, s1=0.f;
                    #pragma unroll
                    for (int i = 0; i < 4; i++) {
                        float4 v = *(const float4*)(hb + (size_t)r*H + i*128 + lane*4);
                        s0 += v.x*wA[i*4]+v.y*wA[i*4+1]+v.z*wA[i*4+2]+v.w*wA[i*4+3];
                        s1 += v.x*wB[i*4]+v.y*wB[i*4+1]+v.z*wB[i*4+2]+v.w*wB[i*4+3];
                    }
                    p0[r]=s0; p1[r]=s1;
                }
            }
            #pragma unroll
            for (int r = 0; r < 8; r++) {
                #pragma unroll
                for (int o = 16; o; o >>= 1) {
                    p0[r] += __shfl_xor_sync(~0u, p0[r], o);
                    p1[r] += __shfl_xor_sync(~0u, p1[r], o);
                }
            }
            if (lane < 8) {
                float a0=0.f, a1=0.f;
                #pragma unroll
                for (int r = 0; r < 8; r++) if (lane == r) { a0 = p0[r]; a1 = p1[r]; }
                float fl0 = a0 + fx0, fl1 = a1 + fx1;
                float h0 = tanhf(w1v[0]*fl0 + w1v[1]*fl1 + vb1[0]);
                float h1 = tanhf(w1v[2]*fl0 + w1v[3]*fl1 + vb1[1]);
                float h2 = tanhf(w1v[4]*fl0 + w1v[5]*fl1 + vb1[2]);
                float h3 = tanhf(w1v[6]*fl0 + w1v[7]*fl1 + vb1[3]);
                float dl = w2d[0]*h0 + w2d[1]*h1 + w2d[2]*h2 + w2d[3]*h3 + db;
                sF[rbase + lane] = sigm(dl);
            }
        }
        __syncthreads();

        // epilogue: sum 4 K-quarter partials + x-part + bias; LSTM update (1 out/thread)
        float fv = sF[rp];
        float pi = sO[(  rp)*LDO + jp]      + sO[(32+rp)*LDO + jp]
                 + sO[(64+rp)*LDO + jp]     + sO[(96+rp)*LDO + jp]      + gi + bI;
        float pu = sO[(  rp)*LDO + 16+jp]   + sO[(32+rp)*LDO + 16+jp]
                 + sO[(64+rp)*LDO + 16+jp]  + sO[(96+rp)*LDO + 16+jp]   + gu + bU;
        float po = sO[(  rp)*LDO + 32+jp]   + sO[(32+rp)*LDO + 32+jp]
                 + sO[(64+rp)*LDO + 32+jp]  + sO[(96+rp)*LDO + 32+jp]   + go + bO;
        cst = fv*cst + sigm(pi)*tanhf(pu);
        float hv = sigm(po)*tanhf(cst);
        out[(size_t)t*BH_ + (size_t)bq*H + jj] = hv;
        if (t == TS-1 && tail) {
            out[TBH_ + (size_t)bq*H + jj] = hv;
            out[TBH_ + BH_ + (size_t)bq*H + jj] = cst;
        }
        __syncthreads();
        if (tid == 0) {
            __threadfence();
            *(volatile unsigned*)&g_flagw[(size_t)t*NGC + blockIdx.x] = 1u;
        }
    }
}

extern "C" void kernel_launch(void* const* d_in, const int* in_sizes, int n_in,
                              void* d_out, int out_size) {
    const float* X   = (const float*)d_in[0];
    const float* Wf  = (const float*)d_in[1];
    const float* bf  = (const float*)d_in[2];
    const float* Wi  = (const float*)d_in[3];
    const float* bi  = (const float*)d_in[4];
    const float* Wu  = (const float*)d_in[5];
    const float* bu  = (const float*)d_in[6];
    const float* Wo  = (const float*)d_in[7];
    const float* bo  = (const float*)d_in[8];
    const float* Ws1 = (const float*)d_in[9];
    const float* bs1 = (const float*)d_in[10];
    const float* Ws2 = (const float*)d_in[11];
    const float* bs2 = (const float*)d_in[12];
    float* out = (float*)d_out;

    cudaFuncSetAttribute(rec_kernel, cudaFuncAttributeMaxDynamicSharedMemorySize, REC_SMEM);
    cudaFuncSetAttribute(gemm_x,     cudaFuncAttributeMaxDynamicSharedMemorySize, GX_SMEM);

    prep_kernel<<<NG3+8, 128>>>(Wi, Wu, Wo, bi, bu, bo);
    prepx_kernel<<<MT*D/1024, 256>>>(X);
    fx_kernel<<<MT/8, 256>>>(X, Wf, bf);
    dim3 g(NG3/128, MT/128);
    gemm_x<<<g, 256, GX_SMEM>>>();
    rec_kernel<<<NGC, 512, REC_SMEM>>>(out, Wf, Ws1, bs1, Ws2, bs2, (long long)out_size);
}